// round 4
// baseline (speedup 1.0000x reference)
#include <cuda_runtime.h>
#include <math.h>
#include <stdint.h>

#define NU 100000
#define NI 100000
#define NE 300000
#define NROWS (NU + NI)
#define G3 384

__device__ int   d_lastU[NU];
__device__ int   d_lastV[NI];
__device__ float d_G1[(size_t)NROWS * G3];   // X @ Wi^T (307 MB)

// ---------------------------------------------------------------------------
__global__ void k_init_last() {
    int i = blockIdx.x * blockDim.x + threadIdx.x;
    if (i < NU) d_lastU[i] = -1;
    if (i < NI) d_lastV[i] = -1;
}

__global__ void k_scan_edges(const int* __restrict__ src, const int* __restrict__ dst) {
    int i = blockIdx.x * blockDim.x + threadIdx.x;
    if (i < NE) {
        atomicMax(&d_lastU[src[i]], i);
        atomicMax(&d_lastV[dst[i]], i);
    }
}

// ---------------------------------------------------------------------------
__device__ __forceinline__ uint32_t f2tf32(float x) {
    uint32_t r; asm("cvt.rna.tf32.f32 %0, %1;" : "=r"(r) : "f"(x)); return r;
}
__device__ __forceinline__ void mma_tf32(float c[4], uint32_t a0, uint32_t a1,
                                         uint32_t a2, uint32_t a3,
                                         uint32_t b0, uint32_t b1) {
    asm volatile(
        "mma.sync.aligned.m16n8k8.row.col.f32.tf32.tf32.f32 "
        "{%0,%1,%2,%3}, {%4,%5,%6,%7}, {%8,%9}, {%0,%1,%2,%3};"
        : "+f"(c[0]), "+f"(c[1]), "+f"(c[2]), "+f"(c[3])
        : "r"(a0), "r"(a1), "r"(a2), "r"(a3), "r"(b0), "r"(b1));
}
__device__ __forceinline__ float sigf(float x) { return 1.f / (1.f + __expf(-x)); }

// ===========================================================================
// Kernel A: fused build-X + GEMM1.  C[128,192] per CTA; grid (1563, 2).
// 8 warps as 2(M) x 4(N); warp tile 64x48 (4 m-tiles x 6 n-tiles of m16n8k8).
// A (X) built on the fly: sections [other|own|cos(t*freq)|e] of 128 cols each.
#define ASMS 136   // A smem k-row stride (words); %32==8 -> conflict-free frags
#define BSMS 200   // B smem k-row stride (words); %32==8

__global__ __launch_bounds__(256, 1)
void k_gemm1(const float* __restrict__ si, const float* __restrict__ sj,
             const float* __restrict__ t,  const float* __restrict__ efeat,
             const int* __restrict__ src,  const int* __restrict__ dst,
             const float* __restrict__ Wi, const float* __restrict__ freq) {
    __shared__ uint32_t As[2][16 * ASMS];
    __shared__ uint32_t Bs[2][16 * BSMS];
    __shared__ int   s_le[128];
    __shared__ int   s_ot[128];
    __shared__ float s_tv[128];

    const int tid = threadIdx.x;
    const int lane = tid & 31;
    const int w  = tid >> 5;
    const int wm = w & 1;
    const int wn = w >> 1;
    const int g  = lane >> 2;
    const int tg = lane & 3;
    const int m0 = blockIdx.x * 128;
    const int n0 = blockIdx.y * 192;

    // per-row metadata
    if (tid < 128) {
        int gr = m0 + tid;
        int le = -1, ot = 0; float tv = 0.f;
        if (gr < NU) {
            le = d_lastU[gr];
            if (le >= 0) { ot = dst[le]; tv = t[le]; }
        } else if (gr < NROWS) {
            le = d_lastV[gr - NU];
            if (le >= 0) { ot = src[le]; tv = t[le]; }
        }
        s_le[tid] = le; s_ot[tid] = ot; s_tv[tid] = tv;
    }
    __syncthreads();

    // A loader: one thread per (row, half): row covers 8 cols of each 16-col chunk
    const int arow = tid & 127;
    const int half = tid >> 7;
    const int gr   = m0 + arow;
    const int le   = s_le[arow];
    const int ot   = s_ot[arow];
    const float tv = s_tv[arow];
    const float* base0 = (gr < NU) ? (sj + (size_t)ot * 128) : (si + (size_t)ot * 128);
    const float* own   = (gr < NU) ? (si + (size_t)gr * 128)
                                   : ((gr < NROWS) ? (sj + (size_t)(gr - NU) * 128) : si);

    // B loader indices: 768 float4 per chunk -> 3 per thread, consecutive rows
    int b_row[3], b_kq[3];
#pragma unroll
    for (int i = 0; i < 3; ++i) {
        int idx = tid + 256 * i;              // 0..767
        b_row[i] = idx % 192;
        b_kq[i]  = idx / 192;                 // 0..3
    }

    float acc[4][6][4];
#pragma unroll
    for (int i = 0; i < 4; ++i)
#pragma unroll
        for (int j = 0; j < 6; ++j)
#pragma unroll
            for (int c = 0; c < 4; ++c) acc[i][j][c] = 0.f;

    float  va[8];
    float4 vb[3];

    // ---- prefetch chunk 0
    {
        const int soff = half * 8;            // c=0 -> sec 0
        if (le >= 0) {
            float4 p = *(const float4*)(base0 + soff);
            float4 q = *(const float4*)(base0 + soff + 4);
            va[0]=p.x; va[1]=p.y; va[2]=p.z; va[3]=p.w;
            va[4]=q.x; va[5]=q.y; va[6]=q.z; va[7]=q.w;
        } else {
#pragma unroll
            for (int k = 0; k < 8; ++k) va[k] = 0.f;
        }
#pragma unroll
        for (int i = 0; i < 3; ++i)
            vb[i] = *(const float4*)(Wi + (size_t)(n0 + b_row[i]) * 512 + b_kq[i] * 4);
    }

    for (int c = 0; c < 32; ++c) {
        const int b = c & 1;
        // store staged regs -> smem (tf32)
#pragma unroll
        for (int i = 0; i < 8; ++i)
            As[b][(half * 8 + i) * ASMS + arow] = f2tf32(va[i]);
#pragma unroll
        for (int i = 0; i < 3; ++i) {
            uint32_t* p = &Bs[b][(b_kq[i] * 4) * BSMS + b_row[i]];
            p[0]        = f2tf32(vb[i].x);
            p[BSMS]     = f2tf32(vb[i].y);
            p[2 * BSMS] = f2tf32(vb[i].z);
            p[3 * BSMS] = f2tf32(vb[i].w);
        }
        __syncthreads();

        // prefetch next chunk
        if (c < 31) {
            const int cn = c + 1;
            const int soff = ((cn & 7) << 4) + half * 8;
            const int sec  = cn >> 3;
            if (le >= 0) {
                if (sec == 0) {
                    float4 p = *(const float4*)(base0 + soff);
                    float4 q = *(const float4*)(base0 + soff + 4);
                    va[0]=p.x; va[1]=p.y; va[2]=p.z; va[3]=p.w;
                    va[4]=q.x; va[5]=q.y; va[6]=q.z; va[7]=q.w;
                } else if (sec == 1) {
                    float4 p = *(const float4*)(own + soff);
                    float4 q = *(const float4*)(own + soff + 4);
                    va[0]=p.x; va[1]=p.y; va[2]=p.z; va[3]=p.w;
                    va[4]=q.x; va[5]=q.y; va[6]=q.z; va[7]=q.w;
                } else if (sec == 2) {
                    float4 p = *(const float4*)(freq + soff);
                    float4 q = *(const float4*)(freq + soff + 4);
                    va[0]=__cosf(tv*p.x); va[1]=__cosf(tv*p.y);
                    va[2]=__cosf(tv*p.z); va[3]=__cosf(tv*p.w);
                    va[4]=__cosf(tv*q.x); va[5]=__cosf(tv*q.y);
                    va[6]=__cosf(tv*q.z); va[7]=__cosf(tv*q.w);
                } else {
                    const float* ep = efeat + (size_t)le * 128 + soff;
                    float4 p = *(const float4*)(ep);
                    float4 q = *(const float4*)(ep + 4);
                    va[0]=p.x; va[1]=p.y; va[2]=p.z; va[3]=p.w;
                    va[4]=q.x; va[5]=q.y; va[6]=q.z; va[7]=q.w;
                }
            } else {
#pragma unroll
                for (int k = 0; k < 8; ++k) va[k] = 0.f;
            }
#pragma unroll
            for (int i = 0; i < 3; ++i)
                vb[i] = *(const float4*)(Wi + (size_t)(n0 + b_row[i]) * 512 +
                                         cn * 16 + b_kq[i] * 4);
        }

        // compute
#pragma unroll
        for (int kk = 0; kk < 16; kk += 8) {
            uint32_t af[4][4], bf[6][2];
#pragma unroll
            for (int im = 0; im < 4; ++im) {
                int m = wm * 64 + im * 16;
                af[im][0] = As[b][(kk + tg) * ASMS + m + g];
                af[im][1] = As[b][(kk + tg) * ASMS + m + g + 8];
                af[im][2] = As[b][(kk + tg + 4) * ASMS + m + g];
                af[im][3] = As[b][(kk + tg + 4) * ASMS + m + g + 8];
            }
#pragma unroll
            for (int in_ = 0; in_ < 6; ++in_) {
                int n = wn * 48 + in_ * 8 + g;
                bf[in_][0] = Bs[b][(kk + tg) * BSMS + n];
                bf[in_][1] = Bs[b][(kk + tg + 4) * BSMS + n];
            }
#pragma unroll
            for (int im = 0; im < 4; ++im)
#pragma unroll
                for (int in_ = 0; in_ < 6; ++in_)
                    mma_tf32(acc[im][in_], af[im][0], af[im][1], af[im][2],
                             af[im][3], bf[in_][0], bf[in_][1]);
        }
        __syncthreads();
    }

    // epilogue -> d_G1
#pragma unroll
    for (int im = 0; im < 4; ++im) {
#pragma unroll
        for (int in_ = 0; in_ < 6; ++in_) {
            int row = m0 + wm * 64 + im * 16 + g;
            int col = n0 + wn * 48 + in_ * 8 + tg * 2;
            if (row < NROWS)
                *(float2*)(d_G1 + (size_t)row * G3 + col) =
                    make_float2(acc[im][in_][0], acc[im][in_][1]);
            if (row + 8 < NROWS)
                *(float2*)(d_G1 + (size_t)(row + 8) * G3 + col) =
                    make_float2(acc[im][in_][2], acc[im][in_][3]);
        }
    }
}

// ===========================================================================
// Kernel B: fused GEMM2 (H @ Wh^T) + GRU combine. 64 rows x 384 cols per CTA.
// 8 warps, each warp tile 64x48 (4 m-tiles x 6 n-tiles). K=128.
#define A2S 72    // A smem k-row stride (words); %32==8
#define B2S 392   // B smem k-row stride (words); %32==8
#define EXS 385   // exchange stride (words); %32==1

#define SMB_AS 0
#define SMB_BS 36864                       // 128*72*4
#define SMB_TOTAL 98560                    // max(36864+2*25088, 64*385*4)

__global__ __launch_bounds__(256, 1)
void k_gemm2(const float* __restrict__ si, const float* __restrict__ sj,
             const float* __restrict__ Wh,
             const float* __restrict__ bi, const float* __restrict__ bh,
             float* __restrict__ out) {
    extern __shared__ char smraw[];
    uint32_t* Asm = (uint32_t*)(smraw + SMB_AS);         // 128 k x 64 rows
    uint32_t (*Bsm)[16 * B2S] = (uint32_t(*)[16 * B2S])(smraw + SMB_BS);
    float* Ex = (float*)smraw;                           // overlay (epilogue)

    const int tid = threadIdx.x;
    const int lane = tid & 31;
    const int w  = tid >> 5;
    const int g  = lane >> 2;
    const int tg = lane & 3;
    const int r0 = blockIdx.x * 64;

    // ---- load A (h rows) once: 2048 float4, 8 per thread
#pragma unroll
    for (int i = 0; i < 8; ++i) {
        int idx = tid + 256 * i;            // 0..2047
        int row = idx & 63;
        int q   = idx >> 6;                 // 0..31 (float4 group along k)
        int grr = r0 + row;
        const float* hp = (grr < NU) ? si + (size_t)grr * 128
                                     : sj + (size_t)(grr - NU) * 128;
        float4 v = *(const float4*)(hp + q * 4);
        uint32_t* p = &Asm[(q * 4) * A2S + row];
        p[0]       = f2tf32(v.x);
        p[A2S]     = f2tf32(v.y);
        p[2 * A2S] = f2tf32(v.z);
        p[3 * A2S] = f2tf32(v.w);
    }

    // B loader indices: 1536 float4 per chunk -> 6 per thread
    int b_row[6], b_kq[6];
#pragma unroll
    for (int i = 0; i < 6; ++i) {
        int idx = tid + 256 * i;            // 0..1535
        b_row[i] = idx % 384;
        b_kq[i]  = idx / 384;               // 0..3
    }

    float acc[4][6][4];
#pragma unroll
    for (int i = 0; i < 4; ++i)
#pragma unroll
        for (int j = 0; j < 6; ++j)
#pragma unroll
            for (int c = 0; c < 4; ++c) acc[i][j][c] = 0.f;

    float4 vb[6];
#pragma unroll
    for (int i = 0; i < 6; ++i)
        vb[i] = *(const float4*)(Wh + (size_t)b_row[i] * 128 + b_kq[i] * 4);

    for (int c = 0; c < 8; ++c) {
        const int b = c & 1;
#pragma unroll
        for (int i = 0; i < 6; ++i) {
            uint32_t* p = &Bsm[b][(b_kq[i] * 4) * B2S + b_row[i]];
            p[0]       = f2tf32(vb[i].x);
            p[B2S]     = f2tf32(vb[i].y);
            p[2 * B2S] = f2tf32(vb[i].z);
            p[3 * B2S] = f2tf32(vb[i].w);
        }
        __syncthreads();
        if (c < 7) {
#pragma unroll
            for (int i = 0; i < 6; ++i)
                vb[i] = *(const float4*)(Wh + (size_t)b_row[i] * 128 +
                                         (c + 1) * 16 + b_kq[i] * 4);
        }
#pragma unroll
        for (int kk = 0; kk < 16; kk += 8) {
            const int kc = c * 16 + kk;
            uint32_t af[4][4], bf[6][2];
#pragma unroll
            for (int im = 0; im < 4; ++im) {
                int m = im * 16;
                af[im][0] = Asm[(kc + tg) * A2S + m + g];
                af[im][1] = Asm[(kc + tg) * A2S + m + g + 8];
                af[im][2] = Asm[(kc + tg + 4) * A2S + m + g];
                af[im][3] = Asm[(kc + tg + 4) * A2S + m + g + 8];
            }
#pragma unroll
            for (int in_ = 0; in_ < 6; ++in_) {
                int n = w * 48 + in_ * 8 + g;
                bf[in_][0] = Bsm[b][(kk + tg) * B2S + n];
                bf[in_][1] = Bsm[b][(kk + tg + 4) * B2S + n];
            }
#pragma unroll
            for (int im = 0; im < 4; ++im)
#pragma unroll
                for (int in_ = 0; in_ < 6; ++in_)
                    mma_tf32(acc[im][in_], af[im][0], af[im][1], af[im][2],
                             af[im][3], bf[in_][0], bf[in_][1]);
        }
        __syncthreads();
    }

    // ---- exchange: acc -> Ex[64][384] (overlays As/Bs)
    __syncthreads();
#pragma unroll
    for (int im = 0; im < 4; ++im) {
#pragma unroll
        for (int in_ = 0; in_ < 6; ++in_) {
            int row = im * 16 + g;
            int col = w * 48 + in_ * 8 + tg * 2;
            Ex[row * EXS + col]           = acc[im][in_][0];
            Ex[row * EXS + col + 1]       = acc[im][in_][1];
            Ex[(row + 8) * EXS + col]     = acc[im][in_][2];
            Ex[(row + 8) * EXS + col + 1] = acc[im][in_][3];
        }
    }
    __syncthreads();

    // ---- combine: warp w handles rows w*8 .. w*8+7
#pragma unroll 1
    for (int r8 = 0; r8 < 8; ++r8) {
        int lrow = w * 8 + r8;
        int grr  = r0 + lrow;
        const float* hp = (grr < NU) ? si + (size_t)grr * 128
                                     : sj + (size_t)(grr - NU) * 128;
        const float* g1 = d_G1 + (size_t)grr * G3;
        float* op = out + (size_t)grr * 128;
#pragma unroll
        for (int j2 = 0; j2 < 4; ++j2) {
            int j = j2 * 32 + lane;
            float ghr = Ex[lrow * EXS + j]       + bh[j];
            float ghz = Ex[lrow * EXS + 128 + j] + bh[128 + j];
            float ghn = Ex[lrow * EXS + 256 + j] + bh[256 + j];
            float gir = g1[j]       + bi[j];
            float giz = g1[128 + j] + bi[128 + j];
            float gin = g1[256 + j] + bi[256 + j];
            float rr = sigf(gir + ghr);
            float zz = sigf(giz + ghz);
            float nn = tanhf(gin + rr * ghn);
            op[j] = (1.f - zz) * nn + zz * hp[j];
        }
    }
}

// ---------------------------------------------------------------------------
extern "C" void kernel_launch(void* const* d_in, const int* in_sizes, int n_in,
                              void* d_out, int out_size) {
    const float* si   = (const float*)d_in[0];
    const float* sj   = (const float*)d_in[1];
    const float* t    = (const float*)d_in[2];
    const float* ef   = (const float*)d_in[3];
    const int*   src  = (const int*)d_in[4];
    const int*   dst  = (const int*)d_in[5];
    const float* Wi   = (const float*)d_in[6];
    const float* Wh   = (const float*)d_in[7];
    const float* bi   = (const float*)d_in[8];
    const float* bh   = (const float*)d_in[9];
    const float* freq = (const float*)d_in[10];
    float* out = (float*)d_out;

    k_init_last<<<(NU + 255) / 256, 256>>>();
    k_scan_edges<<<(NE + 255) / 256, 256>>>(src, dst);

    dim3 gridA((NROWS + 127) / 128, 2);
    k_gemm1<<<gridA, 256>>>(si, sj, t, ef, src, dst, Wi, freq);

    cudaFuncSetAttribute(k_gemm2, cudaFuncAttributeMaxDynamicSharedMemorySize, SMB_TOTAL);
    k_gemm2<<<NROWS / 64, 256, SMB_TOTAL>>>(si, sj, Wh, bi, bh, out);
}

// round 5
// speedup vs baseline: 1.7902x; 1.7902x over previous
#include <cuda_runtime.h>
#include <cuda_fp16.h>
#include <math.h>
#include <stdint.h>

#define NU 100000
#define NI 100000
#define NE 300000
#define NROWS (NU + NI)
#define G3 384
#define MDIM 512

__device__ int    d_lastU[NU];
__device__ int    d_lastV[NI];
__device__ __half d_X[(size_t)NROWS * MDIM];  // mail, fp16 (205 MB)
__device__ __half d_H[(size_t)NROWS * 128];   // h rows, fp16 (51 MB)
__device__ float  d_G1[(size_t)NROWS * G3];
__device__ float  d_G2[(size_t)NROWS * G3];

// ---------------------------------------------------------------------------
__global__ void k_init_last() {
    int i = blockIdx.x * blockDim.x + threadIdx.x;
    if (i < NU) d_lastU[i] = -1;
    if (i < NI) d_lastV[i] = -1;
}

__global__ void k_scan_edges(const int* __restrict__ src, const int* __restrict__ dst) {
    int i = blockIdx.x * blockDim.x + threadIdx.x;
    if (i < NE) {
        atomicMax(&d_lastU[src[i]], i);
        atomicMax(&d_lastV[dst[i]], i);
    }
}

// K2: build X rows (fp16) + H rows (fp16)
__global__ void k_build_x(const float* __restrict__ si, const float* __restrict__ sj,
                          const float* __restrict__ t,  const float* __restrict__ efeat,
                          const int* __restrict__ src,  const int* __restrict__ dst,
                          const float* __restrict__ freq) {
    int r = blockIdx.x;
    int j = threadIdx.x;  // 0..127
    __half* xr = d_X + (size_t)r * MDIM;

    int le; int other; float own;
    if (r < NU) {
        le = d_lastU[r];
        other = (le >= 0) ? dst[le] : 0;
        own = si[(size_t)r * 128 + j];
    } else {
        int v = r - NU;
        le = d_lastV[v];
        other = (le >= 0) ? src[le] : 0;
        own = sj[(size_t)v * 128 + j];
    }
    d_H[(size_t)r * 128 + j] = __float2half(own);

    if (le < 0) {
        xr[j] = __float2half(0.f); xr[j + 128] = __float2half(0.f);
        xr[j + 256] = __float2half(0.f); xr[j + 384] = __float2half(0.f);
        return;
    }
    float ov = (r < NU) ? sj[(size_t)other * 128 + j] : si[(size_t)other * 128 + j];
    float tv = t[le];
    xr[j]       = __float2half(ov);
    xr[j + 128] = __float2half(own);
    xr[j + 256] = __float2half(cosf(tv * freq[j]));
    xr[j + 384] = __float2half(efeat[(size_t)le * 128 + j]);
}

// ---------------------------------------------------------------------------
__device__ __forceinline__ void mma_f16(float c[4], uint32_t a0, uint32_t a1,
                                        uint32_t a2, uint32_t a3,
                                        uint32_t b0, uint32_t b1) {
    asm volatile(
        "mma.sync.aligned.m16n8k16.row.col.f32.f16.f16.f32 "
        "{%0,%1,%2,%3}, {%4,%5,%6,%7}, {%8,%9}, {%0,%1,%2,%3};"
        : "+f"(c[0]), "+f"(c[1]), "+f"(c[2]), "+f"(c[3])
        : "r"(a0), "r"(a1), "r"(a2), "r"(a3), "r"(b0), "r"(b1));
}
__device__ __forceinline__ uint32_t h2u(__half2 h) {
    return *(uint32_t*)&h;
}
__device__ __forceinline__ float sigf(float x) { return 1.f / (1.f + expf(-x)); }

// ---------------------------------------------------------------------------
// C[M,384] = A[M,K]@B[384,K]^T, fp16 operands, f32 accum. 128x128 tile, BK=32.
// 8 warps 2(M)x4(N), warp tile 64x32, m16n8k16.
// Smem: half2-packed, k-pair major: As[kp][m], stride 136 words (%32==8).
#define SMS 136

__global__ __launch_bounds__(256, 2)
void k_hgemm(int a_sel,                         // 0 = d_X, 1 = d_H
             const float* __restrict__ Bf,      // weights [384, K] float
             int c_sel,                          // 0 = d_G1, 1 = d_G2
             int K) {
    __shared__ uint32_t As[2][16 * SMS];
    __shared__ uint32_t Bs[2][16 * SMS];

    const __half* A = a_sel ? d_H : d_X;
    const int lda = a_sel ? 128 : MDIM;
    float* C = c_sel ? d_G2 : d_G1;

    const int tid = threadIdx.x;
    const int lane = tid & 31;
    const int w  = tid >> 5;
    const int wm = w & 1;
    const int wn = w >> 1;
    const int g  = lane >> 2;
    const int tg = lane & 3;
    const int m0 = blockIdx.x * 128;
    const int n0 = blockIdx.y * 128;

    float acc[4][4][4];
#pragma unroll
    for (int i = 0; i < 4; ++i)
#pragma unroll
        for (int j = 0; j < 4; ++j)
#pragma unroll
            for (int c = 0; c < 4; ++c) acc[i][j][c] = 0.f;

    // A loader: 512 uint4 per chunk (128 rows x 4 groups of 8 halves); 2/thread
    const int ar0 = (tid + 0)   >> 2, akq0 = (tid + 0)   & 3;
    const int ar1 = (tid + 256) >> 2, akq1 = (tid + 256) & 3;
    const bool aok0 = (m0 + ar0) < NROWS;
    const bool aok1 = (m0 + ar1) < NROWS;
    const __half* Ap0 = A + (size_t)(m0 + ar0) * lda + akq0 * 8;
    const __half* Ap1 = A + (size_t)(m0 + ar1) * lda + akq1 * 8;

    // B loader: 1024 float4 per chunk (128 rows x 8 f4); 4/thread
    int brow[4], bq[4];
#pragma unroll
    for (int i = 0; i < 4; ++i) {
        int idx = tid + 256 * i;
        brow[i] = idx & 127;
        bq[i]   = idx >> 7;     // 0..7
    }

    uint4  pa0, pa1;
    float4 pb[4];

    const uint4 z4 = make_uint4(0, 0, 0, 0);
    pa0 = aok0 ? *(const uint4*)(Ap0) : z4;
    pa1 = aok1 ? *(const uint4*)(Ap1) : z4;
#pragma unroll
    for (int i = 0; i < 4; ++i)
        pb[i] = *(const float4*)(Bf + (size_t)(n0 + brow[i]) * K + bq[i] * 4);

    const int nchunks = K >> 5;
    for (int c = 0; c < nchunks; ++c) {
        const int b = c & 1;
        // stage -> smem
        {
            uint32_t* p0 = &As[b][(akq0 * 4) * SMS + ar0];
            p0[0] = pa0.x; p0[SMS] = pa0.y; p0[2 * SMS] = pa0.z; p0[3 * SMS] = pa0.w;
            uint32_t* p1 = &As[b][(akq1 * 4) * SMS + ar1];
            p1[0] = pa1.x; p1[SMS] = pa1.y; p1[2 * SMS] = pa1.z; p1[3 * SMS] = pa1.w;
        }
#pragma unroll
        for (int i = 0; i < 4; ++i) {
            uint32_t h0 = h2u(__floats2half2_rn(pb[i].x, pb[i].y));
            uint32_t h1 = h2u(__floats2half2_rn(pb[i].z, pb[i].w));
            uint32_t* p = &Bs[b][(bq[i] * 2) * SMS + brow[i]];
            p[0] = h0; p[SMS] = h1;
        }
        __syncthreads();

        // prefetch next
        if (c + 1 < nchunks) {
            const int ko = (c + 1) * 32;
            pa0 = aok0 ? *(const uint4*)(Ap0 + ko) : z4;
            pa1 = aok1 ? *(const uint4*)(Ap1 + ko) : z4;
#pragma unroll
            for (int i = 0; i < 4; ++i)
                pb[i] = *(const float4*)(Bf + (size_t)(n0 + brow[i]) * K + ko + bq[i] * 4);
        }

        // compute: 2 x k16 steps
#pragma unroll
        for (int kk = 0; kk < 2; ++kk) {
            const int kp = kk * 8;   // kp base for this k16 step
            uint32_t af[4][4], bf2[4][2];
#pragma unroll
            for (int im = 0; im < 4; ++im) {
                int m = wm * 64 + im * 16;
                af[im][0] = As[b][(kp + tg) * SMS + m + g];
                af[im][1] = As[b][(kp + tg) * SMS + m + g + 8];
                af[im][2] = As[b][(kp + tg + 4) * SMS + m + g];
                af[im][3] = As[b][(kp + tg + 4) * SMS + m + g + 8];
            }
#pragma unroll
            for (int in_ = 0; in_ < 4; ++in_) {
                int n = wn * 32 + in_ * 8 + g;
                bf2[in_][0] = Bs[b][(kp + tg) * SMS + n];
                bf2[in_][1] = Bs[b][(kp + tg + 4) * SMS + n];
            }
#pragma unroll
            for (int im = 0; im < 4; ++im)
#pragma unroll
                for (int in_ = 0; in_ < 4; ++in_)
                    mma_f16(acc[im][in_], af[im][0], af[im][1], af[im][2],
                            af[im][3], bf2[in_][0], bf2[in_][1]);
        }
        __syncthreads();
    }

    // epilogue
#pragma unroll
    for (int im = 0; im < 4; ++im) {
#pragma unroll
        for (int in_ = 0; in_ < 4; ++in_) {
            int row = m0 + wm * 64 + im * 16 + g;
            int col = n0 + wn * 32 + in_ * 8 + tg * 2;
            if (row < NROWS)
                *(float2*)(C + (size_t)row * G3 + col) =
                    make_float2(acc[im][in_][0], acc[im][in_][1]);
            if (row + 8 < NROWS)
                *(float2*)(C + (size_t)(row + 8) * G3 + col) =
                    make_float2(acc[im][in_][2], acc[im][in_][3]);
        }
    }
}

// ---------------------------------------------------------------------------
// K5: GRU gate combine + output
__global__ void k_combine(const float* __restrict__ si, const float* __restrict__ sj,
                          const float* __restrict__ bi, const float* __restrict__ bh,
                          float* __restrict__ out) {
    int r = blockIdx.x;
    int j = threadIdx.x;  // 0..127
    const float* g1 = d_G1 + (size_t)r * G3;
    const float* g2 = d_G2 + (size_t)r * G3;

    float h = (r < NU) ? si[(size_t)r * 128 + j] : sj[(size_t)(r - NU) * 128 + j];

    float gir = g1[j]       + bi[j];
    float giz = g1[j + 128] + bi[j + 128];
    float gin = g1[j + 256] + bi[j + 256];
    float ghr = g2[j]       + bh[j];
    float ghz = g2[j + 128] + bh[j + 128];
    float ghn = g2[j + 256] + bh[j + 256];

    float rr = sigf(gir + ghr);
    float zz = sigf(giz + ghz);
    float nn = tanhf(gin + rr * ghn);

    out[(size_t)r * 128 + j] = (1.f - zz) * nn + zz * h;
}

// ---------------------------------------------------------------------------
extern "C" void kernel_launch(void* const* d_in, const int* in_sizes, int n_in,
                              void* d_out, int out_size) {
    const float* si   = (const float*)d_in[0];
    const float* sj   = (const float*)d_in[1];
    const float* t    = (const float*)d_in[2];
    const float* ef   = (const float*)d_in[3];
    const int*   src  = (const int*)d_in[4];
    const int*   dst  = (const int*)d_in[5];
    const float* Wi   = (const float*)d_in[6];
    const float* Wh   = (const float*)d_in[7];
    const float* bi   = (const float*)d_in[8];
    const float* bh   = (const float*)d_in[9];
    const float* freq = (const float*)d_in[10];
    float* out = (float*)d_out;

    k_init_last<<<(NU + 255) / 256, 256>>>();
    k_scan_edges<<<(NE + 255) / 256, 256>>>(src, dst);
    k_build_x<<<NROWS, 128>>>(si, sj, t, ef, src, dst, freq);

    dim3 grid((NROWS + 127) / 128, 3);
    k_hgemm<<<grid, 256>>>(0, Wi, 0, MDIM);   // G1 = X @ Wi^T
    k_hgemm<<<grid, 256>>>(1, Wh, 1, 128);    // G2 = H @ Wh^T

    k_combine<<<NROWS, 128>>>(si, sj, bi, bh, out);
}

// round 6
// speedup vs baseline: 2.8980x; 1.6188x over previous
#include <cuda_runtime.h>
#include <cuda_fp16.h>
#include <math.h>
#include <stdint.h>

#define NU 100000
#define NI 100000
#define NE 300000
#define NROWS (NU + NI)
#define NPAD 200064            // 1563 * 128
#define G3 384
#define MDIM 512

__device__ int    d_lastU[NU];
__device__ int    d_lastV[NI];
__device__ __half d_X[(size_t)NPAD * MDIM];   // mail fp16 (padded rows stay 0)
__device__ __half d_H[(size_t)NPAD * 128];    // h fp16
__device__ __half d_hWi[G3 * MDIM];
__device__ __half d_hWh[G3 * 128];
__device__ float  d_G1[(size_t)NROWS * G3];
__device__ float  d_G2[(size_t)NROWS * G3];

// ---------------------------------------------------------------------------
__global__ void k_init_last() {
    int i = blockIdx.x * blockDim.x + threadIdx.x;
    if (i < NU) d_lastU[i] = -1;
    if (i < NI) d_lastV[i] = -1;
}

__global__ void k_scan_edges(const int* __restrict__ src, const int* __restrict__ dst) {
    int i = blockIdx.x * blockDim.x + threadIdx.x;
    if (i < NE) {
        atomicMax(&d_lastU[src[i]], i);
        atomicMax(&d_lastV[dst[i]], i);
    }
}

__global__ void k_cvt_w(const float* __restrict__ Wi, const float* __restrict__ Wh) {
    int i = blockIdx.x * blockDim.x + threadIdx.x;
    if (i < G3 * MDIM) d_hWi[i] = __float2half(Wi[i]);
    if (i < G3 * 128)  d_hWh[i] = __float2half(Wh[i]);
}

// K2: build X rows (fp16) + H rows (fp16)
__global__ void k_build_x(const float* __restrict__ si, const float* __restrict__ sj,
                          const float* __restrict__ t,  const float* __restrict__ efeat,
                          const int* __restrict__ src,  const int* __restrict__ dst,
                          const float* __restrict__ freq) {
    int r = blockIdx.x;
    int j = threadIdx.x;  // 0..127
    __half* xr = d_X + (size_t)r * MDIM;

    int le; int other; float own;
    if (r < NU) {
        le = d_lastU[r];
        other = (le >= 0) ? dst[le] : 0;
        own = si[(size_t)r * 128 + j];
    } else {
        int v = r - NU;
        le = d_lastV[v];
        other = (le >= 0) ? src[le] : 0;
        own = sj[(size_t)v * 128 + j];
    }
    d_H[(size_t)r * 128 + j] = __float2half(own);

    if (le < 0) {
        xr[j] = __float2half(0.f); xr[j + 128] = __float2half(0.f);
        xr[j + 256] = __float2half(0.f); xr[j + 384] = __float2half(0.f);
        return;
    }
    float ov = (r < NU) ? sj[(size_t)other * 128 + j] : si[(size_t)other * 128 + j];
    float tv = t[le];
    xr[j]       = __float2half(ov);
    xr[j + 128] = __float2half(own);
    xr[j + 256] = __float2half(cosf(tv * freq[j]));
    xr[j + 384] = __float2half(efeat[(size_t)le * 128 + j]);
}

// ---------------------------------------------------------------------------
__device__ __forceinline__ uint32_t smem_u32(const void* p) {
    uint32_t a;
    asm("{ .reg .u64 t; cvta.to.shared.u64 t, %1; cvt.u32.u64 %0, t; }" : "=r"(a) : "l"(p));
    return a;
}
__device__ __forceinline__ void cp16(uint32_t dst, const void* src) {
    asm volatile("cp.async.cg.shared.global [%0], [%1], 16;"
                 :: "r"(dst), "l"(src) : "memory");
}
#define CP_COMMIT() asm volatile("cp.async.commit_group;" ::: "memory")
#define CP_WAIT2()  asm volatile("cp.async.wait_group 2;" ::: "memory")

__device__ __forceinline__ void ldsm4(uint32_t& r0, uint32_t& r1, uint32_t& r2,
                                      uint32_t& r3, uint32_t a) {
    asm volatile("ldmatrix.sync.aligned.m8n8.x4.shared.b16 {%0,%1,%2,%3}, [%4];"
                 : "=r"(r0), "=r"(r1), "=r"(r2), "=r"(r3) : "r"(a));
}
__device__ __forceinline__ void mma_f16(float c[4], uint32_t a0, uint32_t a1,
                                        uint32_t a2, uint32_t a3,
                                        uint32_t b0, uint32_t b1) {
    asm volatile(
        "mma.sync.aligned.m16n8k16.row.col.f32.f16.f16.f32 "
        "{%0,%1,%2,%3}, {%4,%5,%6,%7}, {%8,%9}, {%0,%1,%2,%3};"
        : "+f"(c[0]), "+f"(c[1]), "+f"(c[2]), "+f"(c[3])
        : "r"(a0), "r"(a1), "r"(a2), "r"(a3), "r"(b0), "r"(b1));
}
__device__ __forceinline__ float sigf(float x) { return 1.f / (1.f + expf(-x)); }

// swizzled byte offset within a [128 rows x 32 halves] tile (64B rows, 16B units)
__device__ __forceinline__ uint32_t sw_off(int m, int u) {
    return (uint32_t)((m << 6) + (((u ^ ((m >> 1) & 3)) & 3) << 4));
}

// ---------------------------------------------------------------------------
// C[M,384] = A[M,K] @ B[384,K]^T, fp16/f32. 128x128 CTA tile, BK=32,
// 4-stage cp.async pipeline, ldmatrix fragments, warp tile 64x32 (2x4 warps).
#define STG_BYTES 16384   // A 8KB + B 8KB per stage
#define SMEM_TOT  (4 * STG_BYTES)

__global__ __launch_bounds__(256, 2)
void k_hgemm(int sel, int K) {
    extern __shared__ char smraw[];
    const uint32_t sb = smem_u32(smraw);

    const __half* A  = sel ? d_H   : d_X;
    const __half* Bw = sel ? d_hWh : d_hWi;
    const int lda    = sel ? 128 : MDIM;
    float* C         = sel ? d_G2 : d_G1;

    const int tid  = threadIdx.x;
    const int lane = tid & 31;
    const int w    = tid >> 5;
    const int wm   = w & 1;
    const int wn   = w >> 1;
    const int g    = lane >> 2;
    const int tg   = lane & 3;
    const int m0   = blockIdx.x * 128;
    const int n0   = blockIdx.y * 128;

    // cp.async loader: thread -> (row = tid>>1, units u0, u0+1)
    const int lrow = tid >> 1;
    const int u0   = (tid & 1) * 2;
    const __half* aP = A  + (size_t)(m0 + lrow) * lda + u0 * 8;
    const __half* bP = Bw + (size_t)(n0 + lrow) * K   + u0 * 8;
    const uint32_t dA0 = sw_off(lrow, u0);
    const uint32_t dA1 = sw_off(lrow, u0 + 1);

    // ldmatrix per-lane offsets (within-tile bytes)
    uint32_t offA[4][2], offB[2][2];
    {
        const int mr = ((lane >> 3) & 1) * 8 + (lane & 7);
        const int uu = lane >> 4;   // 0 or 1
#pragma unroll
        for (int im = 0; im < 4; ++im)
#pragma unroll
            for (int kk = 0; kk < 2; ++kk)
                offA[im][kk] = sw_off(wm * 64 + im * 16 + mr, kk * 2 + uu);
#pragma unroll
        for (int j = 0; j < 2; ++j)
#pragma unroll
            for (int kk = 0; kk < 2; ++kk)
                offB[j][kk] = 8192u + sw_off(wn * 32 + j * 16 + mr, kk * 2 + uu);
    }

    float acc[4][4][4];
#pragma unroll
    for (int i = 0; i < 4; ++i)
#pragma unroll
        for (int j = 0; j < 4; ++j)
#pragma unroll
            for (int c = 0; c < 4; ++c) acc[i][j][c] = 0.f;

    const int nch = K >> 5;

    // prologue: 3 stages in flight
#pragma unroll
    for (int s = 0; s < 3; ++s) {
        const uint32_t st = sb + s * STG_BYTES;
        cp16(st + dA0,         aP + s * 32);
        cp16(st + dA1,         aP + s * 32 + 8);
        cp16(st + 8192 + dA0,  bP + s * 32);
        cp16(st + 8192 + dA1,  bP + s * 32 + 8);
        CP_COMMIT();
    }

    for (int c = 0; c < nch; ++c) {
        CP_WAIT2();
        __syncthreads();

        if (c + 3 < nch) {
            const uint32_t st = sb + ((c + 3) & 3) * STG_BYTES;
            cp16(st + dA0,        aP + (c + 3) * 32);
            cp16(st + dA1,        aP + (c + 3) * 32 + 8);
            cp16(st + 8192 + dA0, bP + (c + 3) * 32);
            cp16(st + 8192 + dA1, bP + (c + 3) * 32 + 8);
        }
        CP_COMMIT();

        const uint32_t stg = sb + (c & 3) * STG_BYTES;
#pragma unroll
        for (int kk = 0; kk < 2; ++kk) {
            uint32_t a[4][4], b[2][4];
#pragma unroll
            for (int im = 0; im < 4; ++im)
                ldsm4(a[im][0], a[im][1], a[im][2], a[im][3], stg + offA[im][kk]);
#pragma unroll
            for (int j = 0; j < 2; ++j)
                ldsm4(b[j][0], b[j][1], b[j][2], b[j][3], stg + offB[j][kk]);
#pragma unroll
            for (int im = 0; im < 4; ++im) {
                mma_f16(acc[im][0], a[im][0], a[im][1], a[im][2], a[im][3],
                        b[0][0], b[0][2]);
                mma_f16(acc[im][1], a[im][0], a[im][1], a[im][2], a[im][3],
                        b[0][1], b[0][3]);
                mma_f16(acc[im][2], a[im][0], a[im][1], a[im][2], a[im][3],
                        b[1][0], b[1][2]);
                mma_f16(acc[im][3], a[im][0], a[im][1], a[im][2], a[im][3],
                        b[1][1], b[1][3]);
            }
        }
    }

    // epilogue
#pragma unroll
    for (int im = 0; im < 4; ++im) {
#pragma unroll
        for (int in_ = 0; in_ < 4; ++in_) {
            const int row = m0 + wm * 64 + im * 16 + g;
            const int col = n0 + wn * 32 + in_ * 8 + tg * 2;
            if (row < NROWS)
                *(float2*)(C + (size_t)row * G3 + col) =
                    make_float2(acc[im][in_][0], acc[im][in_][1]);
            if (row + 8 < NROWS)
                *(float2*)(C + (size_t)(row + 8) * G3 + col) =
                    make_float2(acc[im][in_][2], acc[im][in_][3]);
        }
    }
}

// ---------------------------------------------------------------------------
__global__ void k_combine(const float* __restrict__ si, const float* __restrict__ sj,
                          const float* __restrict__ bi, const float* __restrict__ bh,
                          float* __restrict__ out) {
    int r = blockIdx.x;
    int j = threadIdx.x;  // 0..127
    const float* g1 = d_G1 + (size_t)r * G3;
    const float* g2 = d_G2 + (size_t)r * G3;

    float h = (r < NU) ? si[(size_t)r * 128 + j] : sj[(size_t)(r - NU) * 128 + j];

    float gir = g1[j]       + bi[j];
    float giz = g1[j + 128] + bi[j + 128];
    float gin = g1[j + 256] + bi[j + 256];
    float ghr = g2[j]       + bh[j];
    float ghz = g2[j + 128] + bh[j + 128];
    float ghn = g2[j + 256] + bh[j + 256];

    float rr = sigf(gir + ghr);
    float zz = sigf(giz + ghz);
    float nn = tanhf(gin + rr * ghn);

    out[(size_t)r * 128 + j] = (1.f - zz) * nn + zz * h;
}

// ---------------------------------------------------------------------------
extern "C" void kernel_launch(void* const* d_in, const int* in_sizes, int n_in,
                              void* d_out, int out_size) {
    const float* si   = (const float*)d_in[0];
    const float* sj   = (const float*)d_in[1];
    const float* t    = (const float*)d_in[2];
    const float* ef   = (const float*)d_in[3];
    const int*   src  = (const int*)d_in[4];
    const int*   dst  = (const int*)d_in[5];
    const float* Wi   = (const float*)d_in[6];
    const float* Wh   = (const float*)d_in[7];
    const float* bi   = (const float*)d_in[8];
    const float* bh   = (const float*)d_in[9];
    const float* freq = (const float*)d_in[10];
    float* out = (float*)d_out;

    k_init_last<<<(NU + 255) / 256, 256>>>();
    k_scan_edges<<<(NE + 255) / 256, 256>>>(src, dst);
    k_cvt_w<<<(G3 * MDIM + 255) / 256, 256>>>(Wi, Wh);
    k_build_x<<<NROWS, 128>>>(si, sj, t, ef, src, dst, freq);

    cudaFuncSetAttribute(k_hgemm, cudaFuncAttributeMaxDynamicSharedMemorySize, SMEM_TOT);
    dim3 grid(NPAD / 128, 3);
    k_hgemm<<<grid, 256, SMEM_TOT>>>(0, MDIM);   // G1 = X @ Wi^T
    k_hgemm<<<grid, 256, SMEM_TOT>>>(1, 128);    // G2 = H @ Wh^T

    k_combine<<<NROWS, 128>>>(si, sj, bi, bh, out);
}